// round 5
// baseline (speedup 1.0000x reference)
#include <cuda_runtime.h>

#define N_NODES 100000
#define D 128
#define YCOLS 768   // 6 blocks of 128: [r1 | r2p0 r2p1 | r3p0 r3p1 r3p2]

// ---------------- device scratch (no allocations allowed) ----------------
__device__ float g_Y[(size_t)N_NODES * YCOLS];   // ~307 MB
__device__ int   g_deg[3 * N_NODES];
__device__ unsigned int g_hi_or;                  // 0 => edge dtype is int64

// index fetch that works for both int64 and int32 edge buffers
__device__ __forceinline__ int edge_at(const void* ei, long long pos, bool is64) {
    if (is64) return (int)((const long long*)ei)[pos];
    return ((const int*)ei)[pos];
}

// ---------------- init + dtype probe ----------------
__global__ void init_kernel(const void* __restrict__ e1) {
    int i = blockIdx.x * blockDim.x + threadIdx.x;
    if (i < 3 * N_NODES) g_deg[i] = 0;
    if (i == 0) g_hi_or = 0u;
}

__global__ void detect_kernel(const void* __restrict__ e1) {
    // look at the first 128 odd int32 words: all zero <=> int64 layout
    const unsigned int* w = (const unsigned int*)e1;
    unsigned int v = w[2 * threadIdx.x + 1];
    // warp-reduce then one atomic per warp
    for (int o = 16; o > 0; o >>= 1) v |= __shfl_down_sync(0xffffffffu, v, o);
    if ((threadIdx.x & 31) == 0 && v) atomicOr(&g_hi_or, v);
}

// ---------------- degree count ----------------
__global__ void count_deg_kernel(const void* __restrict__ ei,
                                 int n_edges, int S, int toff) {
    int e = blockIdx.x * blockDim.x + threadIdx.x;
    if (e >= n_edges) return;
    bool is64 = (g_hi_or == 0u);
    long long n = (long long)n_edges * S;           // elements per row
    int dest = edge_at(ei, n + (long long)e * S, is64);   // ei[1][e*S]
    atomicAdd(&g_deg[toff + dest], 1);
}

// ---------------- fused GEMM: Y = X @ [A blocks], out = X @ C_w + C_b ----------------
struct WPtrs { const float* W[7]; };

#define TM 128
#define TN 128
#define KC 32

__global__ __launch_bounds__(256, 2) void gemm_kernel(
    const float* __restrict__ X, WPtrs wp,
    const float* __restrict__ Cb, float* __restrict__ out)
{
    __shared__ float Xs[KC][TM + 1];  // [k][m], padded -> conflict-free
    __shared__ float Ws[KC][TN];      // [k][n]

    const int b  = blockIdx.y;        // weight block 0..6 (6 == C_w)
    const float* __restrict__ W = wp.W[b];
    const int m0 = blockIdx.x * TM;
    const int t  = threadIdx.x;
    const int tx = t & 15;            // 16 col-threads
    const int ty = t >> 4;            // 16 row-threads

    float acc[8][8];
#pragma unroll
    for (int i = 0; i < 8; i++)
#pragma unroll
        for (int j = 0; j < 8; j++) acc[i][j] = 0.f;

    for (int k0 = 0; k0 < D; k0 += KC) {
        // X tile: 128 rows x KC cols, stored transposed Xs[k][m]
#pragma unroll
        for (int i = t; i < TM * KC; i += 256) {
            int row = i >> 5;          // /KC (KC==32)
            int kk  = i & 31;
            int m = m0 + row;
            Xs[kk][row] = (m < N_NODES) ? X[(size_t)m * D + k0 + kk] : 0.f;
        }
        // W tile: KC rows x 128 cols
#pragma unroll
        for (int i = t; i < KC * TN; i += 256) {
            int kk = i >> 7;           // /TN (TN==128)
            int n  = i & 127;
            Ws[kk][n] = W[(size_t)(k0 + kk) * TN + n];
        }
        __syncthreads();

#pragma unroll
        for (int kk = 0; kk < KC; kk++) {
            float xr[8], wr[8];
#pragma unroll
            for (int i = 0; i < 8; i++) xr[i] = Xs[kk][ty * 8 + i];
#pragma unroll
            for (int j = 0; j < 8; j++) wr[j] = Ws[kk][tx * 8 + j];
#pragma unroll
            for (int i = 0; i < 8; i++)
#pragma unroll
                for (int j = 0; j < 8; j++)
                    acc[i][j] += xr[i] * wr[j];
        }
        __syncthreads();
    }

    if (b == 6) {
        // out = X @ C_w + C_b
#pragma unroll
        for (int i = 0; i < 8; i++) {
            int m = m0 + ty * 8 + i;
            if (m < N_NODES) {
#pragma unroll
                for (int j = 0; j < 8; j++)
                    out[(size_t)m * D + tx * 8 + j] = acc[i][j] + Cb[tx * 8 + j];
            }
        }
    } else {
        const int coff = b * 128;
#pragma unroll
        for (int i = 0; i < 8; i++) {
            int m = m0 + ty * 8 + i;
            if (m < N_NODES) {
#pragma unroll
                for (int j = 0; j < 8; j++)
                    g_Y[(size_t)m * YCOLS + coff + tx * 8 + j] = acc[i][j];
            }
        }
    }
}

// ---------------- edge aggregation: gather Y rows, scale by 1/deg, scatter-add ----------------
template <int S>
__global__ __launch_bounds__(256) void edge_kernel(
    const void* __restrict__ ei, int n_edges,
    int ycoloff, int toff, float* __restrict__ out)
{
    int warp = (blockIdx.x * blockDim.x + threadIdx.x) >> 5;
    int lane = threadIdx.x & 31;
    if (warp >= n_edges) return;
    bool is64 = (g_hi_or == 0u);

    long long n    = (long long)n_edges * S;
    long long base = (long long)warp * S;
    int dest = edge_at(ei, n + base, is64);            // ei[1][e*S]
    float scale = 1.0f / (float)g_deg[toff + dest];

    float4 acc = make_float4(0.f, 0.f, 0.f, 0.f);
#pragma unroll
    for (int p = 0; p < S; p++) {
        int src = edge_at(ei, base + p, is64);         // ei[0][e*S+p]
        const float4* yp = (const float4*)(g_Y + (size_t)src * YCOLS + ycoloff + p * D);
        float4 v = yp[lane];
        acc.x += v.x; acc.y += v.y; acc.z += v.z; acc.w += v.w;
    }
    acc.x *= scale; acc.y *= scale; acc.z *= scale; acc.w *= scale;

    float* op = out + (size_t)dest * D + lane * 4;
    asm volatile("red.global.add.v4.f32 [%0], {%1, %2, %3, %4};"
                 :: "l"(op), "f"(acc.x), "f"(acc.y), "f"(acc.z), "f"(acc.w)
                 : "memory");
}

// ---------------- launch ----------------
extern "C" void kernel_launch(void* const* d_in, const int* in_sizes, int n_in,
                              void* d_out, int out_size)
{
    const float *x = nullptr, *A1 = nullptr, *A2 = nullptr, *A3 = nullptr,
                *Cw = nullptr, *Cb = nullptr;
    const void *e1 = nullptr, *e2 = nullptr, *e3 = nullptr;

    for (int i = 0; i < n_in; i++) {
        int s = in_sizes[i];
        if      (s == 12800000) x  = (const float*)d_in[i];
        else if (s == 800000)   e1 = d_in[i];
        else if (s == 1200000)  { if (!e2) e2 = d_in[i];
                                  else      e3 = d_in[i]; }
        else if (s == 32768)    A2 = (const float*)d_in[i];
        else if (s == 49152)    A3 = (const float*)d_in[i];
        else if (s == 16384)    { if (!A1) A1 = (const float*)d_in[i];
                                  else      Cw = (const float*)d_in[i]; }
        else if (s == 128)      Cb = (const float*)d_in[i];
    }
    float* out = (float*)d_out;

    // 1) init + dtype probe + degrees
    init_kernel<<<(3 * N_NODES + 255) / 256, 256>>>(e1);
    detect_kernel<<<1, 128>>>(e1);
    count_deg_kernel<<<(400000 + 255) / 256, 256>>>(e1, 400000, 1, 0);
    count_deg_kernel<<<(300000 + 255) / 256, 256>>>(e2, 300000, 2, N_NODES);
    count_deg_kernel<<<(200000 + 255) / 256, 256>>>(e3, 200000, 3, 2 * N_NODES);

    // 2) fused GEMM: Y blocks + (x@C_w + C_b) into out
    WPtrs wp;
    wp.W[0] = A1;
    wp.W[1] = A2;               wp.W[2] = A2 + 128 * 128;
    wp.W[3] = A3;               wp.W[4] = A3 + 128 * 128;  wp.W[5] = A3 + 2 * 128 * 128;
    wp.W[6] = Cw;
    dim3 grid((N_NODES + TM - 1) / TM, 7);
    gemm_kernel<<<grid, 256>>>(x, wp, Cb, out);

    // 3) edge aggregation (1 warp per hyperedge)
    edge_kernel<1><<<(400000 + 7) / 8, 256>>>(e1, 400000, 0,   0,           out);
    edge_kernel<2><<<(300000 + 7) / 8, 256>>>(e2, 300000, 128, N_NODES,     out);
    edge_kernel<3><<<(200000 + 7) / 8, 256>>>(e3, 200000, 384, 2 * N_NODES, out);
}

// round 10
// speedup vs baseline: 2.2230x; 2.2230x over previous
#include <cuda_runtime.h>
#include <cstdint>

#define N_NODES 100000
#define D 128
#define TCOLS 768   // 6 scatter blocks of 128: [r1 | r2p0 r2p1 | r3p0 r3p1 r3p2]

// ---------------- device scratch (no allocations allowed) ----------------
__device__ float g_T[(size_t)N_NODES * TCOLS];   // ~307 MB scatter accumulators
__device__ float g_WT[7 * 128 * 128];            // transposed weight blocks (b=6 -> C_w)
__device__ int   g_deg[3 * N_NODES];
__device__ unsigned int g_hi_or;                  // 0 => edge dtype is int64

// ---------------- helpers ----------------
__device__ __forceinline__ uint32_t f2tf(float f) {   // round-to-nearest tf32
    uint32_t r;
    asm("cvt.rna.tf32.f32 %0, %1;" : "=r"(r) : "f"(f));
    return r;
}

// index fetch that works for both int64 and int32 edge buffers
__device__ __forceinline__ int edge_at(const void* ei, long long pos, bool is64) {
    if (is64) return (int)((const long long*)ei)[pos];
    return ((const int*)ei)[pos];
}

// ---------------- zero + dtype probe ----------------
__global__ void zero_kernel() {
    size_t i = (size_t)blockIdx.x * blockDim.x + threadIdx.x;
    const size_t n4 = (size_t)N_NODES * TCOLS / 4;   // 19.2M float4
    if (i < n4) ((float4*)g_T)[i] = make_float4(0.f, 0.f, 0.f, 0.f);
    if (i < 3 * N_NODES) g_deg[i] = 0;
    if (i == 0) g_hi_or = 0u;
}

__global__ void detect_kernel(const void* __restrict__ e1) {
    const unsigned int* w = (const unsigned int*)e1;
    unsigned int v = w[2 * threadIdx.x + 1];
    for (int o = 16; o > 0; o >>= 1) v |= __shfl_down_sync(0xffffffffu, v, o);
    if ((threadIdx.x & 31) == 0 && v) atomicOr(&g_hi_or, v);
}

// ---------------- weight transpose: g_WT[b][n][k] = W_b[k][n] ----------------
struct WPtrs { const float* W[7]; };

__global__ void wt_kernel(WPtrs wp) {
    __shared__ float tile[32][33];
    int b  = blockIdx.y;
    int tr = (blockIdx.x >> 2) * 32;   // k base
    int tc = (blockIdx.x & 3)  * 32;   // n base
    const float* W = wp.W[b];
    int x = threadIdx.x, y = threadIdx.y;   // 32 x 8
#pragma unroll
    for (int i = 0; i < 32; i += 8)
        tile[y + i][x] = W[(size_t)(tr + y + i) * 128 + tc + x];
    __syncthreads();
    float* WT = g_WT + b * 16384;
#pragma unroll
    for (int i = 0; i < 32; i += 8)
        WT[(size_t)(tc + y + i) * 128 + tr + x] = tile[x][y + i];
}

// ---------------- edge scatter: T[dest, block(t,p)] += x[src_p]; deg count ----------------
template <int S>
__global__ __launch_bounds__(256) void edge_kernel(
    const void* __restrict__ ei, int n_edges,
    int colbase, int toff, const float* __restrict__ X)
{
    int warp = (blockIdx.x * blockDim.x + threadIdx.x) >> 5;
    int lane = threadIdx.x & 31;
    if (warp >= n_edges) return;
    bool is64 = (g_hi_or == 0u);

    long long n    = (long long)n_edges * S;
    long long base = (long long)warp * S;
    int dest = edge_at(ei, n + base, is64);            // ei[1][e*S]
    if (lane == 0) atomicAdd(&g_deg[toff + dest], 1);

    float* trow = g_T + (size_t)dest * TCOLS + colbase;
#pragma unroll
    for (int p = 0; p < S; p++) {
        int src = edge_at(ei, base + p, is64);         // ei[0][e*S+p]
        float4 v = ((const float4*)(X + (size_t)src * D))[lane];
        float* op = trow + p * D + lane * 4;
        asm volatile("red.global.add.v4.f32 [%0], {%1, %2, %3, %4};"
                     :: "l"(op), "f"(v.x), "f"(v.y), "f"(v.z), "f"(v.w)
                     : "memory");
    }
}

// ---------------- tf32 mma.sync GEMM ----------------
// out = sum_b (T_b * inv_deg) @ A_b^T  +  x @ C_w  + C_b      (K = 7*128 = 896)
// CTA tile 128(m) x 128(n); 8 warps, each 32m x 64n; K chunks of 32.
// SMEM stride 36 floats -> fragment LDS bank-conflict-free (bank = 4*gid+tig).
#define KSTRIDE 36

__global__ __launch_bounds__(256, 2) void tgemm_kernel(
    const float* __restrict__ X, const float* __restrict__ Cb,
    float* __restrict__ out)
{
    __shared__ uint32_t As[128 * KSTRIDE];
    __shared__ uint32_t Bs[128 * KSTRIDE];
    __shared__ float    inv_s[3 * 128];

    const int t    = threadIdx.x;
    const int lane = t & 31;
    const int wid  = t >> 5;
    const int gid  = lane >> 2;     // 0..7
    const int tig  = lane & 3;      // 0..3
    const int m0   = blockIdx.x * 128;
    const int mrem = N_NODES - m0;

    const int mbase = (wid & 3) * 32;    // warp m offset
    const int nbase = (wid >> 2) * 64;   // warp n offset

    if (t < 128) {
#pragma unroll
        for (int tt = 0; tt < 3; tt++) {
            int d = (t < mrem) ? g_deg[tt * N_NODES + m0 + t] : 0;
            inv_s[tt * 128 + t] = d ? (1.0f / (float)d) : 0.0f;
        }
    }
    __syncthreads();

    float acc[2][8][4];
#pragma unroll
    for (int mt = 0; mt < 2; mt++)
#pragma unroll
        for (int nt = 0; nt < 8; nt++)
#pragma unroll
            for (int r = 0; r < 4; r++) acc[mt][nt][r] = 0.f;

    for (int c = 0; c < 28; c++) {
        const int b    = c >> 2;          // weight block 0..6 (6 == C_w / x)
        const int koff = (c & 3) * 32;
        const int tt   = (b == 0) ? 0 : (b < 3) ? 1 : 2;

        // stage A (activations, 128 rows x 32 k) and B (W^T, 128 n x 32 k)
#pragma unroll
        for (int it = 0; it < 4; it++) {
            int slot = t + it * 256;      // 0..1023
            int row = slot >> 3, f4 = slot & 7;

            float4 v = make_float4(0.f, 0.f, 0.f, 0.f);
            if (row < mrem) {
                if (b == 6) {
                    v = *(const float4*)(X + (size_t)(m0 + row) * D + koff + f4 * 4);
                } else {
                    v = *(const float4*)(g_T + (size_t)(m0 + row) * TCOLS
                                         + b * 128 + koff + f4 * 4);
                    float s = inv_s[tt * 128 + row];
                    v.x *= s; v.y *= s; v.z *= s; v.w *= s;
                }
            }
            uint32_t* da = As + row * KSTRIDE + f4 * 4;
            da[0] = f2tf(v.x); da[1] = f2tf(v.y); da[2] = f2tf(v.z); da[3] = f2tf(v.w);

            float4 w = *(const float4*)(g_WT + b * 16384 + (size_t)row * 128
                                        + koff + f4 * 4);
            uint32_t* db = Bs + row * KSTRIDE + f4 * 4;
            db[0] = f2tf(w.x); db[1] = f2tf(w.y); db[2] = f2tf(w.z); db[3] = f2tf(w.w);
        }
        __syncthreads();

#pragma unroll
        for (int ks = 0; ks < 4; ks++) {
            const int k0 = ks * 8 + tig;
            uint32_t a[2][4];
#pragma unroll
            for (int mt = 0; mt < 2; mt++) {
                int rm = mbase + mt * 16;
                a[mt][0] = As[(rm + gid)     * KSTRIDE + k0];
                a[mt][1] = As[(rm + 8 + gid) * KSTRIDE + k0];
                a[mt][2] = As[(rm + gid)     * KSTRIDE + k0 + 4];
                a[mt][3] = As[(rm + 8 + gid) * KSTRIDE + k0 + 4];
            }
#pragma unroll
            for (int nt = 0; nt < 8; nt++) {
                uint32_t b0 = Bs[(nbase + nt * 8 + gid) * KSTRIDE + k0];
                uint32_t b1 = Bs[(nbase + nt * 8 + gid) * KSTRIDE + k0 + 4];
#pragma unroll
                for (int mt = 0; mt < 2; mt++) {
                    float* dd = acc[mt][nt];
                    asm volatile(
                        "mma.sync.aligned.m16n8k8.row.col.f32.tf32.tf32.f32 "
                        "{%0,%1,%2,%3}, {%4,%5,%6,%7}, {%8,%9}, {%0,%1,%2,%3};"
                        : "+f"(dd[0]), "+f"(dd[1]), "+f"(dd[2]), "+f"(dd[3])
                        : "r"(a[mt][0]), "r"(a[mt][1]), "r"(a[mt][2]), "r"(a[mt][3]),
                          "r"(b0), "r"(b1));
                }
            }
        }
        __syncthreads();
    }

    // epilogue: out = acc + C_b
#pragma unroll
    for (int nt = 0; nt < 8; nt++) {
        int col = nbase + nt * 8 + 2 * tig;
        float cb0 = __ldg(&Cb[col]), cb1 = __ldg(&Cb[col + 1]);
#pragma unroll
        for (int mt = 0; mt < 2; mt++) {
            int m = m0 + mbase + mt * 16 + gid;
            if (m < N_NODES) {
                float2 v = make_float2(acc[mt][nt][0] + cb0, acc[mt][nt][1] + cb1);
                *(float2*)(out + (size_t)m * D + col) = v;
            }
            if (m + 8 < N_NODES) {
                float2 v = make_float2(acc[mt][nt][2] + cb0, acc[mt][nt][3] + cb1);
                *(float2*)(out + (size_t)(m + 8) * D + col) = v;
            }
        }
    }
}

// ---------------- launch ----------------
extern "C" void kernel_launch(void* const* d_in, const int* in_sizes, int n_in,
                              void* d_out, int out_size)
{
    const float *x = nullptr, *A1 = nullptr, *A2 = nullptr, *A3 = nullptr,
                *Cw = nullptr, *Cb = nullptr;
    const void *e1 = nullptr, *e2 = nullptr, *e3 = nullptr;

    for (int i = 0; i < n_in; i++) {
        int s = in_sizes[i];
        if      (s == 12800000) x  = (const float*)d_in[i];
        else if (s == 800000)   e1 = d_in[i];
        else if (s == 1200000)  { if (!e2) e2 = d_in[i];
                                  else      e3 = d_in[i]; }
        else if (s == 32768)    A2 = (const float*)d_in[i];
        else if (s == 49152)    A3 = (const float*)d_in[i];
        else if (s == 16384)    { if (!A1) A1 = (const float*)d_in[i];
                                  else      Cw = (const float*)d_in[i]; }
        else if (s == 128)      Cb = (const float*)d_in[i];
    }
    float* out = (float*)d_out;

    // 1) zero scratch + dtype probe + weight transpose
    zero_kernel<<<((N_NODES * TCOLS / 4) + 255) / 256, 256>>>();
    detect_kernel<<<1, 128>>>(e1);
    WPtrs wp;
    wp.W[0] = A1;
    wp.W[1] = A2;               wp.W[2] = A2 + 128 * 128;
    wp.W[3] = A3;               wp.W[4] = A3 + 128 * 128;  wp.W[5] = A3 + 2 * 128 * 128;
    wp.W[6] = Cw;
    wt_kernel<<<dim3(16, 7), dim3(32, 8)>>>(wp);

    // 2) edge scatter of raw x rows into T (+ fused degree counts)
    edge_kernel<1><<<(400000 + 7) / 8, 256>>>(e1, 400000, 0,   0,           x);
    edge_kernel<2><<<(300000 + 7) / 8, 256>>>(e2, 300000, 128, N_NODES,     x);
    edge_kernel<3><<<(200000 + 7) / 8, 256>>>(e3, 200000, 384, 2 * N_NODES, x);

    // 3) single accumulating tf32 mma.sync GEMM -> out
    tgemm_kernel<<<(N_NODES + 127) / 128, 256>>>(x, Cb, out);
}